// round 10
// baseline (speedup 1.0000x reference)
#include <cuda_runtime.h>
#include <cuda_fp16.h>
#include <math.h>

#define TT 4096
#define EMB 512
#define HID 2048
#define NCH 256
#define NCOLS 8192            // 4*HID
#define NCTA 128
#define HPB 16                // hidden units per CTA (2 warps each)
#define THR 1024              // 32 warps
#define NSM 48                // fp16 weight rows in SMEM per CTA (gates 0,1,2)

// Static device scratch (allocation-free rule: __device__ globals only)
__device__ __half g_Wth[(size_t)NCOLS * HID];   // fp16 Wt[gate*2048+j][k] = Wg[(512+k)*2048+j]
__device__ float  g_Zx[(size_t)TT * NCOLS];     // input-part preactivations (+bias), fp32
__device__ float  g_hs[(size_t)TT * HID];       // hidden states per step, fp32
__device__ unsigned g_bar;

__device__ __forceinline__ unsigned ldacq(const unsigned* p) {
    unsigned v;
    asm volatile("ld.acquire.gpu.u32 %0, [%1];" : "=r"(v) : "l"(p) : "memory");
    return v;
}

__global__ void bar_init_kernel() { g_bar = 0u; }

// ---------------------------------------------------------------------------
// K0: transpose hidden-part of gate weights into row-per-output-column layout,
//     converting to fp16 (weights are N(0, 0.02^2): far inside fp16 range)
// ---------------------------------------------------------------------------
__global__ __launch_bounds__(256) void wt_transpose_kernel(
    const float* __restrict__ W0, const float* __restrict__ W1,
    const float* __restrict__ W2, const float* __restrict__ W3)
{
    __shared__ float tile[32][33];
    int g = blockIdx.z;
    const float* W = (g == 0) ? W0 : (g == 1) ? W1 : (g == 2) ? W2 : W3;
    int k0 = blockIdx.x * 32;
    int j0 = blockIdx.y * 32;
    int tx = threadIdx.x & 31;
    int ty = threadIdx.x >> 5;

#pragma unroll
    for (int i = 0; i < 4; ++i) {
        int r = ty + i * 8;
        tile[r][tx] = W[(size_t)(EMB + k0 + r) * HID + (j0 + tx)];
    }
    __syncthreads();
#pragma unroll
    for (int i = 0; i < 4; ++i) {
        int r = ty + i * 8;
        g_Wth[((size_t)g * HID + (j0 + r)) * HID + (k0 + tx)] = __float2half(tile[tx][r]);
    }
}

// ---------------------------------------------------------------------------
// K1: Zx[t][g*2048+j] = emb[idx[t]] @ Wg[:512] + bg   (M=4096,N=8192,K=512)
//     fp32 throughout (input path precision preserved)
// ---------------------------------------------------------------------------
__global__ __launch_bounds__(256) void zx_gemm_kernel(
    const int* __restrict__ idx, const float* __restrict__ emb,
    const float* __restrict__ W0, const float* __restrict__ W1,
    const float* __restrict__ W2, const float* __restrict__ W3,
    const float* __restrict__ b0, const float* __restrict__ b1,
    const float* __restrict__ b2, const float* __restrict__ b3)
{
    __shared__ float As[64][17];
    __shared__ float Bs[16][64];
    __shared__ int idx_s[64];

    int m0 = blockIdx.x * 64;
    int n0 = blockIdx.y * 64;
    int gate = n0 >> 11;
    int j0 = n0 & (HID - 1);
    const float* W = (gate == 0) ? W0 : (gate == 1) ? W1 : (gate == 2) ? W2 : W3;
    const float* bias = (gate == 0) ? b0 : (gate == 1) ? b1 : (gate == 2) ? b2 : b3;

    int tid = threadIdx.x;
    int tx = tid & 15, ty = tid >> 4;

    if (tid < 64) idx_s[tid] = idx[m0 + tid];
    __syncthreads();

    float acc[4][4] = {};
    for (int k0 = 0; k0 < EMB; k0 += 16) {
        {
            int kk = tid & 15;
            int mmb = tid >> 4;
#pragma unroll
            for (int r = 0; r < 4; ++r) {
                int mm = mmb + r * 16;
                As[mm][kk] = emb[(size_t)idx_s[mm] * EMB + k0 + kk];
            }
        }
        {
            int nn = tid & 63;
            int kkb = tid >> 6;
#pragma unroll
            for (int r = 0; r < 4; ++r) {
                int kk = kkb + r * 4;
                Bs[kk][nn] = W[(size_t)(k0 + kk) * HID + j0 + nn];
            }
        }
        __syncthreads();
#pragma unroll
        for (int kk = 0; kk < 16; ++kk) {
            float a[4];
#pragma unroll
            for (int i = 0; i < 4; ++i) a[i] = As[ty * 4 + i][kk];
            float4 bv = *(const float4*)&Bs[kk][tx * 4];
            float b[4] = {bv.x, bv.y, bv.z, bv.w};
#pragma unroll
            for (int i = 0; i < 4; ++i)
#pragma unroll
                for (int j = 0; j < 4; ++j) acc[i][j] += a[i] * b[j];
        }
        __syncthreads();
    }
#pragma unroll
    for (int i = 0; i < 4; ++i) {
        int m = m0 + ty * 4 + i;
#pragma unroll
        for (int j = 0; j < 4; ++j) {
            int n = n0 + tx * 4 + j;
            g_Zx[(size_t)m * NCOLS + n] = acc[i][j] + bias[j0 + tx * 4 + j];
        }
    }
}

// ---------------------------------------------------------------------------
// K2: persistent recurrent LSTM — fp16 weights + split-K two-warps-per-unit.
// 128 CTAs x 1024 threads (32 warps, 8/SMSP). Unit u = w>>1; half = w&1
// covers k in [half*1024, half*1024+1024). Each warp: 4 gate rows of its
// unit over its k-half (8 iters). Weights fp16: gates 0,1,2 in SMEM
// (48 rows x 4KB = 192KB), gate-3 half-row pinned in RF (8 uint2 = 16 regs).
// NO LDG in the mainloop. h fp32; fp16->fp32 cvt feeds fp32 FFMA.
// Odd warp publishes 4 partials via SMEM; even warp lane0 combines + gates.
// FIX vs R9: k-half offset in uint2 units is half*256 (1024 halves = 256
// uint2), not half*128.
// ---------------------------------------------------------------------------
#define SMEM_BYTES (HID * 4 + NSM * HID * 2 + 64 * 4)

__global__ __launch_bounds__(THR, 1) void lstm_seq_kernel(
    const float* __restrict__ hidden0, const float* __restrict__ cell0,
    float* __restrict__ dout)
{
    extern __shared__ float smem[];
    float*  h_sh  = smem;                            // fp32 [2048]
    __half* wc    = (__half*)(smem + HID);           // fp16 [48][2048]
    float*  zpart = (float*)(wc + (size_t)NSM * HID); // [16][4] odd-warp partials

    const int cta  = blockIdx.x;
    const int tid  = threadIdx.x;
    const int w    = tid >> 5;           // warp 0..31
    const int lane = tid & 31;
    const int u    = w >> 1;             // unit 0..15
    const int half = w & 1;              // k-half
    const int hid0 = cta * HPB;
    const int koff2 = half * 256;        // uint2 offset: 1024 halves = 256 uint2
    const int koff4 = half * 256;        // float4 offset: 1024 floats = 256 float4

    // fill SMEM weight cache: slot = gate*16 + u, gates 0..2 (fp16 copy)
    for (int slot = 0; slot < NSM; ++slot) {
        int gate = slot >> 4;
        int uu   = slot & 15;
        const uint2* src4 = (const uint2*)(g_Wth + ((size_t)gate * HID + hid0 + uu) * HID);
        uint2* dst4 = (uint2*)(wc + (size_t)slot * HID);
        for (int k = tid; k < HID / 4; k += THR) dst4[k] = src4[k];
    }

    // pin gate-3 half-row in registers as fp16: 8 x uint2 = 16 regs
    const uint2* w3g = (const uint2*)(g_Wth + ((size_t)3 * HID + hid0 + u) * HID) + koff2;
    uint2 w3r[8];
#pragma unroll
    for (int i = 0; i < 8; ++i) w3r[i] = w3g[i * 32 + lane];

    // cell state: even-warp lane 0
    float c = 0.f;
    if (half == 0 && lane == 0) c = cell0[hid0 + u];
    __syncthreads();

    const uint2* p0 = (const uint2*)(wc + (size_t)(0 * 16 + u) * HID) + koff2;
    const uint2* p1 = (const uint2*)(wc + (size_t)(1 * 16 + u) * HID) + koff2;
    const uint2* p2 = (const uint2*)(wc + (size_t)(2 * 16 + u) * HID) + koff2;
    const float4* h4 = (const float4*)h_sh + koff4;
    float4* h4s = (float4*)h_sh;

    for (int t = 0; t < TT; ++t) {
        // Zx prefetch (independent of h), even-warp lane0 only
        float zx0 = 0.f, zx1 = 0.f, zx2 = 0.f, zx3 = 0.f;
        if (half == 0 && lane == 0) {
            const float* zp = g_Zx + (size_t)t * NCOLS + hid0 + u;
            zx0 = zp[0];
            zx1 = zp[HID];
            zx2 = zp[2 * HID];
            zx3 = zp[3 * HID];
        }

        // stage h_{t-1} into SMEM (512 float4, threads 0..511)
        const float4* hprev4 = (t == 0)
            ? (const float4*)hidden0
            : (const float4*)(g_hs + (size_t)(t - 1) * HID);
        if (tid < 512) h4s[tid] = hprev4[tid];
        __syncthreads();

        // matvec over this warp's k-half: 4 gate rows of unit u (no LDG)
        float a0 = 0.f, a1 = 0.f, a2 = 0.f, a3 = 0.f;
#pragma unroll
        for (int i = 0; i < 8; ++i) {
            int i4 = i * 32 + lane;
            float4 hv = h4[i4];                               // LDS.128
            uint2 q0 = p0[i4];                                // LDS.64 (4 halves)
            uint2 q1 = p1[i4];
            uint2 q2 = p2[i4];
            uint2 q3 = w3r[i];                                // regs
            float2 f0a = __half22float2(*(const __half2*)&q0.x);
            float2 f0b = __half22float2(*(const __half2*)&q0.y);
            float2 f1a = __half22float2(*(const __half2*)&q1.x);
            float2 f1b = __half22float2(*(const __half2*)&q1.y);
            float2 f2a = __half22float2(*(const __half2*)&q2.x);
            float2 f2b = __half22float2(*(const __half2*)&q2.y);
            float2 f3a = __half22float2(*(const __half2*)&q3.x);
            float2 f3b = __half22float2(*(const __half2*)&q3.y);
            a0 += f0a.x * hv.x + f0a.y * hv.y + f0b.x * hv.z + f0b.y * hv.w;
            a1 += f1a.x * hv.x + f1a.y * hv.y + f1b.x * hv.z + f1b.y * hv.w;
            a2 += f2a.x * hv.x + f2a.y * hv.y + f2b.x * hv.z + f2b.y * hv.w;
            a3 += f3a.x * hv.x + f3a.y * hv.y + f3b.x * hv.z + f3b.y * hv.w;
        }
#pragma unroll
        for (int off = 16; off; off >>= 1) {
            a0 += __shfl_down_sync(0xffffffffu, a0, off);
            a1 += __shfl_down_sync(0xffffffffu, a1, off);
            a2 += __shfl_down_sync(0xffffffffu, a2, off);
            a3 += __shfl_down_sync(0xffffffffu, a3, off);
        }

        // odd warp publishes partials; even warp keeps its own in regs
        if (half == 1 && lane == 0) {
            float* zb = zpart + u * 4;
            zb[0] = a0; zb[1] = a1; zb[2] = a2; zb[3] = a3;
        }
        __syncthreads();

        // even-warp lane0: combine halves, gate math, store h
        if (half == 0 && lane == 0) {
            const float* zb = zpart + u * 4;
            float zf = a0 + zb[0] + zx0;
            float zi = a1 + zb[1] + zx1;
            float zo = a2 + zb[2] + zx2;
            float zc = a3 + zb[3] + zx3;
            float f  = 1.0f / (1.0f + __expf(-zf));
            float i_ = 1.0f / (1.0f + __expf(-zi));
            float o_ = 1.0f / (1.0f + __expf(-zo));
            float gg = tanhf(zc);
            c = f * c + i_ * gg;
            float hn = o_ * tanhf(c);
            g_hs[(size_t)t * HID + hid0 + u] = hn;
            if (t == TT - 1) {
                dout[(size_t)TT * NCH + hid0 + u] = hn;          // h_fin
                dout[(size_t)TT * NCH + HID + hid0 + u] = c;     // c_fin
            }
        }
        __syncthreads();

        // grid barrier (128 CTAs co-resident, 1/SM)
        if (tid == 0) {
            asm volatile("red.release.gpu.global.add.u32 [%0], %1;"
                         :: "l"(&g_bar), "r"(1u) : "memory");
            unsigned target = (unsigned)(t + 1) * gridDim.x;
            while (ldacq(&g_bar) < target) { }
        }
        __syncthreads();
    }
}

// ---------------------------------------------------------------------------
// K3: out[t][n] = hs[t] @ Wout + bout.  M=4096, N=256, K=2048
// ---------------------------------------------------------------------------
__global__ __launch_bounds__(256) void out_gemm_kernel(
    const float* __restrict__ Wout, const float* __restrict__ bout,
    float* __restrict__ dout)
{
    __shared__ float As[64][17];
    __shared__ float Bs[16][64];

    int m0 = blockIdx.x * 64;
    int n0 = blockIdx.y * 64;
    int tid = threadIdx.x;
    int tx = tid & 15, ty = tid >> 4;

    float acc[4][4] = {};
    for (int k0 = 0; k0 < HID; k0 += 16) {
        {
            int kk = tid & 15;
            int mmb = tid >> 4;
#pragma unroll
            for (int r = 0; r < 4; ++r) {
                int mm = mmb + r * 16;
                As[mm][kk] = g_hs[(size_t)(m0 + mm) * HID + k0 + kk];
            }
        }
        {
            int nn = tid & 63;
            int kkb = tid >> 6;
#pragma unroll
            for (int r = 0; r < 4; ++r) {
                int kk = kkb + r * 4;
                Bs[kk][nn] = Wout[(size_t)(k0 + kk) * NCH + n0 + nn];
            }
        }
        __syncthreads();
#pragma unroll
        for (int kk = 0; kk < 16; ++kk) {
            float a[4];
#pragma unroll
            for (int i = 0; i < 4; ++i) a[i] = As[ty * 4 + i][kk];
            float4 bv = *(const float4*)&Bs[kk][tx * 4];
            float b[4] = {bv.x, bv.y, bv.z, bv.w};
#pragma unroll
            for (int i = 0; i < 4; ++i)
#pragma unroll
                for (int j = 0; j < 4; ++j) acc[i][j] += a[i] * b[j];
        }
        __syncthreads();
    }
#pragma unroll
    for (int i = 0; i < 4; ++i) {
        int m = m0 + ty * 4 + i;
#pragma unroll
        for (int j = 0; j < 4; ++j) {
            int n = n0 + tx * 4 + j;
            dout[(size_t)m * NCH + n] = acc[i][j] + bout[n];
        }
    }
}

// ---------------------------------------------------------------------------
extern "C" void kernel_launch(void* const* d_in, const int* in_sizes, int n_in,
                              void* d_out, int out_size)
{
    const int*   idx    = (const int*)d_in[0];
    const float* hidden = (const float*)d_in[1];
    const float* cell   = (const float*)d_in[2];
    const float* emb    = (const float*)d_in[3];
    const float* Wf     = (const float*)d_in[4];
    const float* bf     = (const float*)d_in[5];
    const float* Wi     = (const float*)d_in[6];
    const float* bi     = (const float*)d_in[7];
    const float* Wo     = (const float*)d_in[8];
    const float* bo     = (const float*)d_in[9];
    const float* Wc     = (const float*)d_in[10];
    const float* bc     = (const float*)d_in[11];
    const float* Wout   = (const float*)d_in[12];
    const float* bout   = (const float*)d_in[13];
    float* out = (float*)d_out;

    cudaFuncSetAttribute(lstm_seq_kernel,
                         cudaFuncAttributeMaxDynamicSharedMemorySize, SMEM_BYTES);

    bar_init_kernel<<<1, 1>>>();
    wt_transpose_kernel<<<dim3(64, 64, 4), 256>>>(Wf, Wi, Wo, Wc);
    zx_gemm_kernel<<<dim3(64, 128), 256>>>(idx, emb, Wf, Wi, Wo, Wc, bf, bi, bo, bc);
    lstm_seq_kernel<<<NCTA, THR, SMEM_BYTES>>>(hidden, cell, out);
    out_gemm_kernel<<<dim3(64, 4), 256>>>(Wout, bout, out);
}

// round 11
// speedup vs baseline: 1.1721x; 1.1721x over previous
#include <cuda_runtime.h>
#include <cuda_fp16.h>
#include <math.h>

#define TT 4096
#define EMB 512
#define HID 2048
#define NCH 256
#define NCOLS 8192            // 4*HID
#define NCTA 128
#define HPB 16                // hidden units per CTA (one warp each)
#define THR 512               // 16 warps

// Static device scratch (allocation-free rule: __device__ globals only)
__device__ __half g_Wth[(size_t)NCOLS * HID];   // fp16 Wt[gate*2048+j][k] = Wg[(512+k)*2048+j]
__device__ float  g_Zx[(size_t)TT * NCOLS];     // input-part preactivations (+bias), fp32
__device__ float  g_hs[(size_t)TT * HID];       // hidden states per step, fp32
__device__ unsigned g_bar;

__device__ __forceinline__ unsigned ldacq(const unsigned* p) {
    unsigned v;
    asm volatile("ld.acquire.gpu.u32 %0, [%1];" : "=r"(v) : "l"(p) : "memory");
    return v;
}
__device__ __forceinline__ float sigmoid_fast(float z) {
    return __fdividef(1.0f, 1.0f + __expf(-z));
}
__device__ __forceinline__ float tanh_fast(float z) {
    float e2 = __expf(-2.0f * z);
    return __fdividef(1.0f - e2, 1.0f + e2);
}

__global__ void bar_init_kernel() { g_bar = 0u; }

// ---------------------------------------------------------------------------
// K0: transpose hidden-part of gate weights into row-per-output-column layout,
//     converting to fp16 (weights are N(0, 0.02^2): far inside fp16 range)
// ---------------------------------------------------------------------------
__global__ __launch_bounds__(256) void wt_transpose_kernel(
    const float* __restrict__ W0, const float* __restrict__ W1,
    const float* __restrict__ W2, const float* __restrict__ W3)
{
    __shared__ float tile[32][33];
    int g = blockIdx.z;
    const float* W = (g == 0) ? W0 : (g == 1) ? W1 : (g == 2) ? W2 : W3;
    int k0 = blockIdx.x * 32;
    int j0 = blockIdx.y * 32;
    int tx = threadIdx.x & 31;
    int ty = threadIdx.x >> 5;

#pragma unroll
    for (int i = 0; i < 4; ++i) {
        int r = ty + i * 8;
        tile[r][tx] = W[(size_t)(EMB + k0 + r) * HID + (j0 + tx)];
    }
    __syncthreads();
#pragma unroll
    for (int i = 0; i < 4; ++i) {
        int r = ty + i * 8;
        g_Wth[((size_t)g * HID + (j0 + r)) * HID + (k0 + tx)] = __float2half(tile[tx][r]);
    }
}

// ---------------------------------------------------------------------------
// K1: Zx[t][g*2048+j] = emb[idx[t]] @ Wg[:512] + bg   (M=4096,N=8192,K=512)
// ---------------------------------------------------------------------------
__global__ __launch_bounds__(256) void zx_gemm_kernel(
    const int* __restrict__ idx, const float* __restrict__ emb,
    const float* __restrict__ W0, const float* __restrict__ W1,
    const float* __restrict__ W2, const float* __restrict__ W3,
    const float* __restrict__ b0, const float* __restrict__ b1,
    const float* __restrict__ b2, const float* __restrict__ b3)
{
    __shared__ float As[64][17];
    __shared__ float Bs[16][64];
    __shared__ int idx_s[64];

    int m0 = blockIdx.x * 64;
    int n0 = blockIdx.y * 64;
    int gate = n0 >> 11;
    int j0 = n0 & (HID - 1);
    const float* W = (gate == 0) ? W0 : (gate == 1) ? W1 : (gate == 2) ? W2 : W3;
    const float* bias = (gate == 0) ? b0 : (gate == 1) ? b1 : (gate == 2) ? b2 : b3;

    int tid = threadIdx.x;
    int tx = tid & 15, ty = tid >> 4;

    if (tid < 64) idx_s[tid] = idx[m0 + tid];
    __syncthreads();

    float acc[4][4] = {};
    for (int k0 = 0; k0 < EMB; k0 += 16) {
        {
            int kk = tid & 15;
            int mmb = tid >> 4;
#pragma unroll
            for (int r = 0; r < 4; ++r) {
                int mm = mmb + r * 16;
                As[mm][kk] = emb[(size_t)idx_s[mm] * EMB + k0 + kk];
            }
        }
        {
            int nn = tid & 63;
            int kkb = tid >> 6;
#pragma unroll
            for (int r = 0; r < 4; ++r) {
                int kk = kkb + r * 4;
                Bs[kk][nn] = W[(size_t)(k0 + kk) * HID + j0 + nn];
            }
        }
        __syncthreads();
#pragma unroll
        for (int kk = 0; kk < 16; ++kk) {
            float a[4];
#pragma unroll
            for (int i = 0; i < 4; ++i) a[i] = As[ty * 4 + i][kk];
            float4 bv = *(const float4*)&Bs[kk][tx * 4];
            float b[4] = {bv.x, bv.y, bv.z, bv.w};
#pragma unroll
            for (int i = 0; i < 4; ++i)
#pragma unroll
                for (int j = 0; j < 4; ++j) acc[i][j] += a[i] * b[j];
        }
        __syncthreads();
    }
#pragma unroll
    for (int i = 0; i < 4; ++i) {
        int m = m0 + ty * 4 + i;
#pragma unroll
        for (int j = 0; j < 4; ++j) {
            int n = n0 + tx * 4 + j;
            g_Zx[(size_t)m * NCOLS + n] = acc[i][j] + bias[j0 + tx * 4 + j];
        }
    }
}

// ---------------------------------------------------------------------------
// K2: persistent recurrent LSTM — fp16 weights, serial-tail optimized.
// 128 CTAs x 512 threads (16 warps). Warp w owns hidden unit hid0+w.
// SMEM: gates 0+1 packed interleaved per unit (uint4 = 4 halves g0 + 4
// halves g1, 128KB) + gate-2 rows (64KB). Gate-3 row pinned in RF (32 regs).
// h_{t-1} read DIRECTLY via LDG (fresh address every step -> L1-safe; 8KB
// L2 misses + 120KB L1 hits/SM/step) — no SMEM staging, 2 syncthreads/step.
// Butterfly reduce -> lanes 0-3 compute the 4 activations in parallel
// (fast sigmoid/tanh via MUFU), lane 0 combines, updates c, stores h.
// ---------------------------------------------------------------------------
#define SMEM_BYTES (HPB * 2048 * 4 + HPB * 1024 * 4)   // 128KB + 64KB

__global__ __launch_bounds__(THR, 1) void lstm_seq_kernel(
    const float* __restrict__ hidden0, const float* __restrict__ cell0,
    float* __restrict__ dout)
{
    extern __shared__ unsigned smem_u[];
    unsigned* wp01 = smem_u;                     // [16][2048] uints: g0|g1 interleaved
    unsigned* wg2  = smem_u + HPB * 2048;        // [16][1024] uints: gate2 rows

    const int cta  = blockIdx.x;
    const int tid  = threadIdx.x;
    const int w    = tid >> 5;          // warp = hidden unit index within CTA
    const int lane = tid & 31;
    const int hid0 = cta * HPB;

    // fill packed g0|g1 SMEM: uint4 i4 of unit u = {g0[2i4],g0[2i4+1],g1[2i4],g1[2i4+1]}
    for (int idx = tid; idx < HPB * 2048; idx += THR) {
        int uu = idx >> 11, r = idx & 2047;
        int i4 = r >> 2, sel = r & 3, gate = sel >> 1, off = sel & 1;
        const unsigned* src = (const unsigned*)(g_Wth + ((size_t)gate * HID + hid0 + uu) * HID);
        wp01[idx] = src[i4 * 2 + off];
    }
    // fill gate-2 SMEM (contiguous)
    for (int idx = tid; idx < HPB * 1024; idx += THR) {
        int uu = idx >> 10, r = idx & 1023;
        const unsigned* src = (const unsigned*)(g_Wth + ((size_t)2 * HID + hid0 + uu) * HID);
        wg2[idx] = src[r];
    }

    // pin gate-3 row in registers as fp16: 16 x uint2 = 32 regs
    const uint2* w3g = (const uint2*)(g_Wth + ((size_t)3 * HID + hid0 + w) * HID);
    uint2 w3r[16];
#pragma unroll
    for (int i = 0; i < 16; ++i) w3r[i] = w3g[i * 32 + lane];

    float c = 0.f;
    if (lane == 0) c = cell0[hid0 + w];
    __syncthreads();

    const uint4* p01 = (const uint4*)(wp01 + (size_t)w * 2048);
    const uint2* p2  = (const uint2*)(wg2  + (size_t)w * 1024);

    for (int t = 0; t < TT; ++t) {
        // Zx prefetch: lanes 0..3 each load their gate's value (overlaps matvec)
        float zx = 0.f;
        if (lane < 4)
            zx = g_Zx[(size_t)t * NCOLS + (size_t)lane * HID + hid0 + w];

        const float4* hsrc = (t == 0)
            ? (const float4*)hidden0
            : (const float4*)(g_hs + (size_t)(t - 1) * HID);

        // matvec: 4 gate rows of unit w; h via LDG, weights SMEM/RF
        float a0 = 0.f, a1 = 0.f, a2 = 0.f, a3 = 0.f;
#pragma unroll
        for (int i = 0; i < 16; ++i) {
            int i4 = i * 32 + lane;
            float4 hv = hsrc[i4];                // LDG.128 (L1 after first warp)
            uint4 q01 = p01[i4];                 // LDS.128: g0 (x,y) | g1 (z,w)
            uint2 q2  = p2[i4];                  // LDS.64
            uint2 q3  = w3r[i];                  // regs
            float2 f0a = __half22float2(*(const __half2*)&q01.x);
            float2 f0b = __half22float2(*(const __half2*)&q01.y);
            float2 f1a = __half22float2(*(const __half2*)&q01.z);
            float2 f1b = __half22float2(*(const __half2*)&q01.w);
            float2 f2a = __half22float2(*(const __half2*)&q2.x);
            float2 f2b = __half22float2(*(const __half2*)&q2.y);
            float2 f3a = __half22float2(*(const __half2*)&q3.x);
            float2 f3b = __half22float2(*(const __half2*)&q3.y);
            a0 += f0a.x * hv.x + f0a.y * hv.y + f0b.x * hv.z + f0b.y * hv.w;
            a1 += f1a.x * hv.x + f1a.y * hv.y + f1b.x * hv.z + f1b.y * hv.w;
            a2 += f2a.x * hv.x + f2a.y * hv.y + f2b.x * hv.z + f2b.y * hv.w;
            a3 += f3a.x * hv.x + f3a.y * hv.y + f3b.x * hv.z + f3b.y * hv.w;
        }
        // butterfly reduce: all lanes end with the 4 full sums
#pragma unroll
        for (int off = 16; off; off >>= 1) {
            a0 += __shfl_xor_sync(0xffffffffu, a0, off);
            a1 += __shfl_xor_sync(0xffffffffu, a1, off);
            a2 += __shfl_xor_sync(0xffffffffu, a2, off);
            a3 += __shfl_xor_sync(0xffffffffu, a3, off);
        }

        // lanes 0..3 compute the 4 activations in parallel
        float act = 0.f;
        if (lane < 4) {
            float s = (lane == 0) ? a0 : (lane == 1) ? a1 : (lane == 2) ? a2 : a3;
            float z = s + zx;
            act = (lane == 3) ? tanh_fast(z) : sigmoid_fast(z);
        }
        float i_ = __shfl_sync(0xffffffffu, act, 1);
        float o_ = __shfl_sync(0xffffffffu, act, 2);
        float g_ = __shfl_sync(0xffffffffu, act, 3);

        // lane 0: cell update (c in register), store h
        if (lane == 0) {
            c = act * c + i_ * g_;               // act = f
            float hn = o_ * tanh_fast(c);
            g_hs[(size_t)t * HID + hid0 + w] = hn;
            if (t == TT - 1) {
                dout[(size_t)TT * NCH + hid0 + w] = hn;          // h_fin
                dout[(size_t)TT * NCH + HID + hid0 + w] = c;     // c_fin
            }
        }
        __syncthreads();

        // grid barrier (128 CTAs co-resident, 1/SM)
        if (tid == 0) {
            asm volatile("red.release.gpu.global.add.u32 [%0], %1;"
                         :: "l"(&g_bar), "r"(1u) : "memory");
            unsigned target = (unsigned)(t + 1) * gridDim.x;
            while (ldacq(&g_bar) < target) { }
        }
        __syncthreads();
    }
}

// ---------------------------------------------------------------------------
// K3: out[t][n] = hs[t] @ Wout + bout.  M=4096, N=256, K=2048
// ---------------------------------------------------------------------------
__global__ __launch_bounds__(256) void out_gemm_kernel(
    const float* __restrict__ Wout, const float* __restrict__ bout,
    float* __restrict__ dout)
{
    __shared__ float As[64][17];
    __shared__ float Bs[16][64];

    int m0 = blockIdx.x * 64;
    int n0 = blockIdx.y * 64;
    int tid = threadIdx.x;
    int tx = tid & 15, ty = tid >> 4;

    float acc[4][4] = {};
    for (int k0 = 0; k0 < HID; k0 += 16) {
        {
            int kk = tid & 15;
            int mmb = tid >> 4;
#pragma unroll
            for (int r = 0; r < 4; ++r) {
                int mm = mmb + r * 16;
                As[mm][kk] = g_hs[(size_t)(m0 + mm) * HID + k0 + kk];
            }
        }
        {
            int nn = tid & 63;
            int kkb = tid >> 6;
#pragma unroll
            for (int r = 0; r < 4; ++r) {
                int kk = kkb + r * 4;
                Bs[kk][nn] = Wout[(size_t)(k0 + kk) * NCH + n0 + nn];
            }
        }
        __syncthreads();
#pragma unroll
        for (int kk = 0; kk < 16; ++kk) {
            float a[4];
#pragma unroll
            for (int i = 0; i < 4; ++i) a[i] = As[ty * 4 + i][kk];
            float4 bv = *(const float4*)&Bs[kk][tx * 4];
            float b[4] = {bv.x, bv.y, bv.z, bv.w};
#pragma unroll
            for (int i = 0; i < 4; ++i)
#pragma unroll
                for (int j = 0; j < 4; ++j) acc[i][j] += a[i] * b[j];
        }
        __syncthreads();
    }
#pragma unroll
    for (int i = 0; i < 4; ++i) {
        int m = m0 + ty * 4 + i;
#pragma unroll
        for (int j = 0; j < 4; ++j) {
            int n = n0 + tx * 4 + j;
            dout[(size_t)m * NCH + n] = acc[i][j] + bout[n];
        }
    }
}

// ---------------------------------------------------------------------------
extern "C" void kernel_launch(void* const* d_in, const int* in_sizes, int n_in,
                              void* d_out, int out_size)
{
    const int*   idx    = (const int*)d_in[0];
    const float* hidden = (const float*)d_in[1];
    const float* cell   = (const float*)d_in[2];
    const float* emb    = (const float*)d_in[3];
    const float* Wf     = (const float*)d_in[4];
    const float* bf     = (const float*)d_in[5];
    const float* Wi     = (const float*)d_in[6];
    const float* bi     = (const float*)d_in[7];
    const float* Wo     = (const float*)d_in[8];
    const float* bo     = (const float*)d_in[9];
    const float* Wc     = (const float*)d_in[10];
    const float* bc     = (const float*)d_in[11];
    const float* Wout   = (const float*)d_in[12];
    const float* bout   = (const float*)d_in[13];
    float* out = (float*)d_out;

    cudaFuncSetAttribute(lstm_seq_kernel,
                         cudaFuncAttributeMaxDynamicSharedMemorySize, SMEM_BYTES);

    bar_init_kernel<<<1, 1>>>();
    wt_transpose_kernel<<<dim3(64, 64, 4), 256>>>(Wf, Wi, Wo, Wc);
    zx_gemm_kernel<<<dim3(64, 128), 256>>>(idx, emb, Wf, Wi, Wo, Wc, bf, bi, bo, bc);
    lstm_seq_kernel<<<NCTA, THR, SMEM_BYTES>>>(hidden, cell, out);
    out_gemm_kernel<<<dim3(64, 4), 256>>>(Wout, bout, out);
}